// round 13
// baseline (speedup 1.0000x reference)
#include <cuda_runtime.h>
#include <cstdint>

#define S_LEN   2048
#define D_MODEL 2048
#define N_TOK   4096        // B*S
#define NH      16
#define NKV     4
#define HD      128
#define QDIM    (NH*HD)     // 2048
#define KVDIM   (NKV*HD)    // 512

// ---------------- scratch (static device globals; no allocation) ----------------
__device__ float g_q[(size_t)N_TOK * QDIM];
__device__ float g_k[(size_t)N_TOK * KVDIM];
__device__ float g_v[(size_t)N_TOK * KVDIM];
__device__ float g_att[(size_t)N_TOK * QDIM];

// ============================================================================
// shared tf32 helpers
// ============================================================================
__device__ __forceinline__ uint32_t f32_to_tf32(float x) {
    uint32_t r;
    asm("cvt.rna.tf32.f32 %0, %1;" : "=r"(r) : "f"(x));
    return r;
}

__device__ __forceinline__ void mma_tf32(
    float& c0, float& c1, float& c2, float& c3,
    uint32_t a0, uint32_t a1, uint32_t a2, uint32_t a3,
    uint32_t b0, uint32_t b1)
{
    asm volatile(
        "mma.sync.aligned.m16n8k8.row.col.f32.tf32.tf32.f32 "
        "{%0,%1,%2,%3}, {%4,%5,%6,%7}, {%8,%9}, {%0,%1,%2,%3};\n"
        : "+f"(c0), "+f"(c1), "+f"(c2), "+f"(c3)
        : "r"(a0), "r"(a1), "r"(a2), "r"(a3), "r"(b0), "r"(b1));
}

// ============================================================================
// tf32 tensor-core GEMM body: C[M,N] = A[M,K] @ B[K,N], row-major fp32 in/out.
// 128x128 tile, BK=32, 256 threads (8 warps 2m x 4n), warp tile 64x32.
// Double-buffered smem: one barrier/tile; STS(t+1) overlaps MMA(t).
// Optional fused RoPE epilogue; optional streaming C stores.
// ============================================================================
#define BM 128
#define BN 128
#define BK 32
#define AS_LD 36    // a-frag banks (4*ga+tg) all distinct
#define BS_LD 136   // b-frag banks (8*tg+ga) all distinct
#define AS_SZ (BM * AS_LD)
#define BS_SZ (BK * BS_LD)

struct GemmSmem {
    uint32_t As[2][AS_SZ];
    uint32_t Bs[2][BS_SZ];
};

__device__ __forceinline__ void gemm_tf32_body(
    GemmSmem& sm,
    const float* __restrict__ A, const float* __restrict__ B, float* __restrict__ C,
    int N, int K, int m0, int n0,
    const float* __restrict__ ropeCos, const float* __restrict__ ropeSin, int doRope,
    int streamC)
{
    const int tid  = threadIdx.x;
    const int lane = tid & 31;
    const int wid  = tid >> 5;
    const int warp_m = wid >> 2;
    const int warp_n = wid & 3;
    const int ga = lane >> 2;
    const int tg = lane & 3;

    // loader indices (constant across tiles)
    const int arow0 = tid >> 3, ac4 = tid & 7;     // + i*32 rows
    const int brow0 = tid >> 5, bc4 = tid & 31;    // + i*8 rows

    float acc[4][4][4];
    #pragma unroll
    for (int i = 0; i < 4; i++)
        #pragma unroll
        for (int j = 0; j < 4; j++)
            #pragma unroll
            for (int r = 0; r < 4; r++) acc[i][j][r] = 0.f;

    float4 aw[4], bw[4];
    // prologue: LDG tile 0, STS into buf 0
    #pragma unroll
    for (int i = 0; i < 4; i++) {
        aw[i] = *(const float4*)&A[(size_t)(m0 + arow0 + i * 32) * K + ac4 * 4];
        bw[i] = *(const float4*)&B[(size_t)(brow0 + i * 8) * N + n0 + bc4 * 4];
    }
    #pragma unroll
    for (int i = 0; i < 4; i++) {
        uint32_t* ap = &sm.As[0][(arow0 + i * 32) * AS_LD + ac4 * 4];
        ap[0] = f32_to_tf32(aw[i].x); ap[1] = f32_to_tf32(aw[i].y);
        ap[2] = f32_to_tf32(aw[i].z); ap[3] = f32_to_tf32(aw[i].w);
        uint32_t* bp = &sm.Bs[0][(brow0 + i * 8) * BS_LD + bc4 * 4];
        bp[0] = f32_to_tf32(bw[i].x); bp[1] = f32_to_tf32(bw[i].y);
        bp[2] = f32_to_tf32(bw[i].z); bp[3] = f32_to_tf32(bw[i].w);
    }
    __syncthreads();

    for (int k0 = 0; k0 < K; k0 += BK) {
        const int buf = (k0 / BK) & 1;
        const int kn = k0 + BK;
        const bool more = (kn < K);

        // LDG next tile (latency hides under MMA below)
        if (more) {
            #pragma unroll
            for (int i = 0; i < 4; i++) {
                aw[i] = *(const float4*)&A[(size_t)(m0 + arow0 + i * 32) * K + kn + ac4 * 4];
                bw[i] = *(const float4*)&B[(size_t)(kn + brow0 + i * 8) * N + n0 + bc4 * 4];
            }
        }

        // MMA on current buffer
        #pragma unroll
        for (int ks = 0; ks < BK / 8; ks++) {
            const int kk = ks * 8;
            uint32_t afr[4][4];
            #pragma unroll
            for (int mt = 0; mt < 4; mt++) {
                const int mrow = warp_m * 64 + mt * 16;
                afr[mt][0] = sm.As[buf][(mrow + ga)     * AS_LD + kk + tg];
                afr[mt][1] = sm.As[buf][(mrow + 8 + ga) * AS_LD + kk + tg];
                afr[mt][2] = sm.As[buf][(mrow + ga)     * AS_LD + kk + 4 + tg];
                afr[mt][3] = sm.As[buf][(mrow + 8 + ga) * AS_LD + kk + 4 + tg];
            }
            uint32_t bfr[4][2];
            #pragma unroll
            for (int nt = 0; nt < 4; nt++) {
                const int ncol = warp_n * 32 + nt * 8;
                bfr[nt][0] = sm.Bs[buf][(kk + tg)     * BS_LD + ncol + ga];
                bfr[nt][1] = sm.Bs[buf][(kk + 4 + tg) * BS_LD + ncol + ga];
            }
            #pragma unroll
            for (int mt = 0; mt < 4; mt++)
                #pragma unroll
                for (int nt = 0; nt < 4; nt++)
                    mma_tf32(acc[mt][nt][0], acc[mt][nt][1], acc[mt][nt][2], acc[mt][nt][3],
                             afr[mt][0], afr[mt][1], afr[mt][2], afr[mt][3],
                             bfr[nt][0], bfr[nt][1]);
        }

        // STS next tile into other buffer (overlaps the tail of MMA issue)
        if (more) {
            const int nb = buf ^ 1;
            #pragma unroll
            for (int i = 0; i < 4; i++) {
                uint32_t* ap = &sm.As[nb][(arow0 + i * 32) * AS_LD + ac4 * 4];
                ap[0] = f32_to_tf32(aw[i].x); ap[1] = f32_to_tf32(aw[i].y);
                ap[2] = f32_to_tf32(aw[i].z); ap[3] = f32_to_tf32(aw[i].w);
                uint32_t* bp = &sm.Bs[nb][(brow0 + i * 8) * BS_LD + bc4 * 4];
                bp[0] = f32_to_tf32(bw[i].x); bp[1] = f32_to_tf32(bw[i].y);
                bp[2] = f32_to_tf32(bw[i].z); bp[3] = f32_to_tf32(bw[i].w);
            }
        }
        __syncthreads();
    }

    // ---- epilogue (optional fused RoPE: rotate (c0,c1)/(c2,c3) pairs) ----
    #pragma unroll
    for (int mt = 0; mt < 4; mt++) {
        const int mrow = m0 + warp_m * 64 + mt * 16;
        #pragma unroll
        for (int nt = 0; nt < 4; nt++) {
            const int ncol = n0 + warp_n * 32 + nt * 8;
            float o0 = acc[mt][nt][0], o1 = acc[mt][nt][1];
            float o2 = acc[mt][nt][2], o3 = acc[mt][nt][3];
            if (doRope) {
                // thread's cols are ncol+2*tg, ncol+2*tg+1 -> pair idx ((ncol&127)>>1)+tg
                const int pi = ((ncol & 127) >> 1) + tg;
                const int s0 = (mrow + ga) & (S_LEN - 1);
                const int s1 = (mrow + 8 + ga) & (S_LEN - 1);
                const float c0 = ropeCos[s0 * 64 + pi], sn0 = ropeSin[s0 * 64 + pi];
                const float c1 = ropeCos[s1 * 64 + pi], sn1 = ropeSin[s1 * 64 + pi];
                const float r0 = o0 * c0 - o1 * sn0, i0 = o0 * sn0 + o1 * c0;
                const float r1 = o2 * c1 - o3 * sn1, i1 = o2 * sn1 + o3 * c1;
                o0 = r0; o1 = i0; o2 = r1; o3 = i1;
            }
            float2* p0 = (float2*)&C[(size_t)(mrow + ga) * N + ncol + 2 * tg];
            float2* p1 = (float2*)&C[(size_t)(mrow + 8 + ga) * N + ncol + 2 * tg];
            if (streamC) {   // final output: never re-read -> evict-first
                __stcs(p0, make_float2(o0, o1));
                __stcs(p1, make_float2(o2, o3));
            } else {
                *p0 = make_float2(o0, o1);
                *p1 = make_float2(o2, o3);
            }
        }
    }
}

// fused QKV projection: grid.x = 16 (q) + 4 (k) + 4 (v) = 24 n-blocks
__global__ __launch_bounds__(256, 2) void qkv_gemm_kernel(
    const float* __restrict__ x,
    const float* __restrict__ wq, const float* __restrict__ wk, const float* __restrict__ wv,
    float* __restrict__ qb, float* __restrict__ kb, float* __restrict__ vb,
    const float* __restrict__ ropeCos, const float* __restrict__ ropeSin)
{
    __shared__ GemmSmem sm;
    const int bx = blockIdx.x;
    const float* B; float* C; int N; int doRope; int nblk;
    if (bx < 16)      { B = wq; C = qb; N = QDIM;  doRope = 1; nblk = bx; }
    else if (bx < 20) { B = wk; C = kb; N = KVDIM; doRope = 1; nblk = bx - 16; }
    else              { B = wv; C = vb; N = KVDIM; doRope = 0; nblk = bx - 20; }
    gemm_tf32_body(sm, x, B, C, N, D_MODEL, blockIdx.y * BM, nblk * BN,
                   ropeCos, ropeSin, doRope, 0);
}

// plain GEMM (wo projection; streaming C stores)
__global__ __launch_bounds__(256, 2) void gemm_tf32_kernel(
    const float* __restrict__ A, const float* __restrict__ B, float* __restrict__ C,
    int N, int K)
{
    __shared__ GemmSmem sm;
    gemm_tf32_body(sm, A, B, C, N, K, blockIdx.y * BM, blockIdx.x * BN,
                   nullptr, nullptr, 0, 1);
}

// ============================================================================
// tensor-core flash attention (causal, GQA), tf32 mma, fp32 online softmax
// in base-2 domain. BM=BN=64, HD=128, 256 threads = 8 warps.
// Pipelined loads: one register buffer tbuf[8] cycles K(t+?)/V(t):
//   [top] STS K(tbuf) ; S-MMA ; LDG V->tbuf ; softmax ; STS V(tbuf) ;
//   LDG K(next)->tbuf ; sync ; PV-MMA (next-K LDG in flight under MMA).
// ============================================================================
#define FQ_LD 132
#define FK_LD 72
#define FV_LD 136
#define FP_LD 68
#define OFF_Q  0
#define OFF_KV (64 * FQ_LD)                 // 8448
#define OFF_P  (OFF_KV + 128 * FK_LD)       // 17664
#define OFF_RM (OFF_P + 64 * FP_LD)         // 22016  red_max[2][64]
#define OFF_RS (OFF_RM + 128)               // 22144  red_sum[2][64]
#define FLASH_SMEM_BYTES ((OFF_RS + 128) * 4)   // 89088

__global__ __launch_bounds__(256, 2) void flash_tc_kernel(
    const float* __restrict__ Q, const float* __restrict__ K,
    const float* __restrict__ V, float* __restrict__ O)
{
    extern __shared__ uint32_t smw[];
    uint32_t* Qs  = smw + OFF_Q;    // [64][132] tf32, row-major [tok][dim]
    uint32_t* KVs = smw + OFF_KV;   // K: [dim][tok^swz] LD 72; V: [tok][dim] LD 136
    uint32_t* Ps  = smw + OFF_P;    // [64][68] tf32
    float* red_m = (float*)(smw + OFF_RM);
    float* red_s = (float*)(smw + OFF_RS);

    const int tid  = threadIdx.x;
    const int lane = tid & 31;
    const int wid  = tid >> 5;
    const int warp_m = wid & 3;
    const int warp_n = wid >> 2;          // 0..1
    const int ga = lane >> 2, tg = lane & 3;
    const int slab = warp_m * 16;

    const int mb = gridDim.x - 1 - blockIdx.x;   // longest CTAs first
    const int h  = blockIdx.y, b = blockIdx.z;
    const int kvh = h >> 2;
    // 1/sqrt(128) * log2(e): scores land directly in base-2 log domain
    const float scale2 = 0.08838834764831845f * 1.4426950408889634f;

    // loader indices (constant across tiles): row lr, dim-quad ld4
    const int lr0 = tid >> 5, ld4 = tid & 31;    // + p*8 rows
    const size_t kvcol = (size_t)kvh * HD + ld4 * 4;

    // ---- load Q tile [64][128] -> Qs (tf32); read-once -> streaming loads ----
    const int qrow0 = b * S_LEN + mb * 64;
    #pragma unroll
    for (int p = 0; p < 8; p++) {
        const int r = lr0 + p * 8;
        const float4 q = __ldcs((const float4*)&Q[(size_t)(qrow0 + r) * QDIM + h * HD + ld4 * 4]);
        uint32_t* qp = &Qs[r * FQ_LD + ld4 * 4];
        qp[0] = f32_to_tf32(q.x); qp[1] = f32_to_tf32(q.y);
        qp[2] = f32_to_tf32(q.z); qp[3] = f32_to_tf32(q.w);
    }

    float m_i[2] = {-1e30f, -1e30f}, l_i[2] = {0.f, 0.f};
    float oacc[8][4];
    #pragma unroll
    for (int t = 0; t < 8; t++)
        #pragma unroll
        for (int r = 0; r < 4; r++) oacc[t][r] = 0.f;

    const int grow0 = mb * 64 + slab + ga;      // global q row (within seq)
    const int grow1 = grow0 + 8;

    // ---- pipeline prologue: prefetch K tile 0 into tbuf ----
    float4 tbuf[8];
    #pragma unroll
    for (int p = 0; p < 8; p++)
        tbuf[p] = *(const float4*)&K[(size_t)(b * S_LEN + lr0 + p * 8) * KVDIM + kvcol];

    for (int kb = 0; kb <= mb; kb++) {
        const int t0 = kb * 64;
        __syncthreads();   // prev PV mma done with KVs/Ps

        // ---- K tile (prefetched in tbuf) -> KVs, d-major with XOR swizzle ----
        #pragma unroll
        for (int p = 0; p < 8; p++) {
            const int r = lr0 + p * 8;
            const int rx = r ^ ld4;             // swizzle: s(d) = (d>>2)&31
            KVs[(ld4 * 4 + 0) * FK_LD + rx] = f32_to_tf32(tbuf[p].x);
            KVs[(ld4 * 4 + 1) * FK_LD + rx] = f32_to_tf32(tbuf[p].y);
            KVs[(ld4 * 4 + 2) * FK_LD + rx] = f32_to_tf32(tbuf[p].z);
            KVs[(ld4 * 4 + 3) * FK_LD + rx] = f32_to_tf32(tbuf[p].w);
        }
        __syncthreads();

        // ---- S = Q @ K^T (64x64), warp tile 16x32 ----
        float sc[4][4];
        #pragma unroll
        for (int nt = 0; nt < 4; nt++)
            #pragma unroll
            for (int j = 0; j < 4; j++) sc[nt][j] = 0.f;

        #pragma unroll
        for (int ks = 0; ks < 16; ks++) {
            const int kk = ks * 8;
            const uint32_t a0 = Qs[(slab + ga)     * FQ_LD + kk + tg];
            const uint32_t a1 = Qs[(slab + 8 + ga) * FQ_LD + kk + tg];
            const uint32_t a2 = Qs[(slab + ga)     * FQ_LD + kk + 4 + tg];
            const uint32_t a3 = Qs[(slab + 8 + ga) * FQ_LD + kk + 4 + tg];
            const int s0 = (2 * ks) & 31, s1 = (2 * ks + 1) & 31;
            #pragma unroll
            for (int nt = 0; nt < 4; nt++) {
                const int ncol = warp_n * 32 + nt * 8;
                const uint32_t b0 = KVs[(kk + tg)     * FK_LD + ((ncol + ga) ^ s0)];
                const uint32_t b1 = KVs[(kk + 4 + tg) * FK_LD + ((ncol + ga) ^ s1)];
                mma_tf32(sc[nt][0], sc[nt][1], sc[nt][2], sc[nt][3],
                         a0, a1, a2, a3, b0, b1);
            }
        }

        // ---- prefetch V tile into tbuf (latency hides under softmax) ----
        #pragma unroll
        for (int p = 0; p < 8; p++)
            tbuf[p] = *(const float4*)&V[(size_t)(b * S_LEN + t0 + lr0 + p * 8) * KVDIM + kvcol];

        // ---- scale into base-2 domain + causal mask (global col > row) ----
        #pragma unroll
        for (int nt = 0; nt < 4; nt++) {
            const int c0 = t0 + warp_n * 32 + nt * 8 + 2 * tg;
            sc[nt][0] = (c0     > grow0) ? -1e30f : sc[nt][0] * scale2;
            sc[nt][1] = (c0 + 1 > grow0) ? -1e30f : sc[nt][1] * scale2;
            sc[nt][2] = (c0     > grow1) ? -1e30f : sc[nt][2] * scale2;
            sc[nt][3] = (c0 + 1 > grow1) ? -1e30f : sc[nt][3] * scale2;
        }

        // ---- row max: 4-lane shuffle + cross-warp smem exchange ----
        float pm0 = -1e30f, pm1 = -1e30f;
        #pragma unroll
        for (int nt = 0; nt < 4; nt++) {
            pm0 = fmaxf(pm0, fmaxf(sc[nt][0], sc[nt][1]));
            pm1 = fmaxf(pm1, fmaxf(sc[nt][2], sc[nt][3]));
        }
        pm0 = fmaxf(pm0, __shfl_xor_sync(0xffffffffu, pm0, 1));
        pm0 = fmaxf(pm0, __shfl_xor_sync(0xffffffffu, pm0, 2));
        pm1 = fmaxf(pm1, __shfl_xor_sync(0xffffffffu, pm1, 1));
        pm1 = fmaxf(pm1, __shfl_xor_sync(0xffffffffu, pm1, 2));
        if (tg == 0) {
            red_m[warp_n * 64 + slab + ga]     = pm0;
            red_m[warp_n * 64 + slab + 8 + ga] = pm1;
        }
        __syncthreads();   // also: all S-mma reads of K complete -> KVs free

        const float mnew0 = fmaxf(m_i[0], fmaxf(red_m[slab + ga],     red_m[64 + slab + ga]));
        const float mnew1 = fmaxf(m_i[1], fmaxf(red_m[slab + 8 + ga], red_m[64 + slab + 8 + ga]));
        const float alpha0 = exp2f(m_i[0] - mnew0);
        const float alpha1 = exp2f(m_i[1] - mnew1);

        // ---- exp2, write P (tf32), partial sums ----
        float ps0 = 0.f, ps1 = 0.f;
        #pragma unroll
        for (int nt = 0; nt < 4; nt++) {
            sc[nt][0] = exp2f(sc[nt][0] - mnew0);
            sc[nt][1] = exp2f(sc[nt][1] - mnew0);
            sc[nt][2] = exp2f(sc[nt][2] - mnew1);
            sc[nt][3] = exp2f(sc[nt][3] - mnew1);
            ps0 += sc[nt][0] + sc[nt][1];
            ps1 += sc[nt][2] + sc[nt][3];
            const int pc = warp_n * 32 + nt * 8 + 2 * tg;
            uint2 u0 = make_uint2(f32_to_tf32(sc[nt][0]), f32_to_tf32(sc[nt][1]));
            uint2 u1 = make_uint2(f32_to_tf32(sc[nt][2]), f32_to_tf32(sc[nt][3]));
            *(uint2*)&Ps[(slab + ga)     * FP_LD + pc] = u0;
            *(uint2*)&Ps[(slab + 8 + ga) * FP_LD + pc] = u1;
        }
        ps0 += __shfl_xor_sync(0xffffffffu, ps0, 1);
        ps0 += __shfl_xor_sync(0xffffffffu, ps0, 2);
        ps1 += __shfl_xor_sync(0xffffffffu, ps1, 1);
        ps1 += __shfl_xor_sync(0xffffffffu, ps1, 2);
        if (tg == 0) {
            red_s[warp_n * 64 + slab + ga]     = ps0;
            red_s[warp_n * 64 + slab + 8 + ga] = ps1;
        }

        // ---- V tile (tbuf) -> KVs (natural [tok][dim], LD 136) ----
        #pragma unroll
        for (int p = 0; p < 8; p++) {
            const int r = lr0 + p * 8;
            uint4 u = make_uint4(f32_to_tf32(tbuf[p].x), f32_to_tf32(tbuf[p].y),
                                 f32_to_tf32(tbuf[p].z), f32_to_tf32(tbuf[p].w));
            *(uint4*)&KVs[r * FV_LD + ld4 * 4] = u;
        }

        // ---- prefetch NEXT K tile into tbuf (hides under PV MMA) ----
        if (kb < mb) {
            #pragma unroll
            for (int p = 0; p < 8; p++)
                tbuf[p] = *(const float4*)&K[(size_t)(b * S_LEN + t0 + 64 + lr0 + p * 8) * KVDIM + kvcol];
        }
        __syncthreads();   // Ps + red_s + V ready

        const float rs0 = red_s[slab + ga]     + red_s[64 + slab + ga];
        const float rs1 = red_s[slab + 8 + ga] + red_s[64 + slab + 8 + ga];
        l_i[0] = l_i[0] * alpha0 + rs0;  m_i[0] = mnew0;
        l_i[1] = l_i[1] * alpha1 + rs1;  m_i[1] = mnew1;
        #pragma unroll
        for (int t = 0; t < 8; t++) {
            oacc[t][0] *= alpha0; oacc[t][1] *= alpha0;
            oacc[t][2] *= alpha1; oacc[t][3] *= alpha1;
        }

        // ---- O += P @ V (64x128, k=64), warp tile 16x64 ----
        #pragma unroll
        for (int ks = 0; ks < 8; ks++) {
            const int kk = ks * 8;
            const uint32_t a0 = Ps[(slab + ga)     * FP_LD + kk + tg];
            const uint32_t a1 = Ps[(slab + 8 + ga) * FP_LD + kk + tg];
            const uint32_t a2 = Ps[(slab + ga)     * FP_LD + kk + 4 + tg];
            const uint32_t a3 = Ps[(slab + 8 + ga) * FP_LD + kk + 4 + tg];
            #pragma unroll
            for (int nt = 0; nt < 8; nt++) {
                const int ncol = warp_n * 64 + nt * 8;
                const uint32_t b0 = KVs[(kk + tg)     * FV_LD + ncol + ga];
                const uint32_t b1 = KVs[(kk + 4 + tg) * FV_LD + ncol + ga];
                mma_tf32(oacc[nt][0], oacc[nt][1], oacc[nt][2], oacc[nt][3],
                         a0, a1, a2, a3, b0, b1);
            }
        }
    }

    // ---- normalize + write ----
    const float inv0 = 1.f / l_i[0], inv1 = 1.f / l_i[1];
    const size_t orow0 = (size_t)(b * S_LEN + grow0) * QDIM + h * HD;
    const size_t orow1 = (size_t)(b * S_LEN + grow1) * QDIM + h * HD;
    #pragma unroll
    for (int nt = 0; nt < 8; nt++) {
        const int col = warp_n * 64 + nt * 8 + 2 * tg;
        *(float2*)&O[orow0 + col] = make_float2(oacc[nt][0] * inv0, oacc[nt][1] * inv0);
        *(float2*)&O[orow1 + col] = make_float2(oacc[nt][2] * inv1, oacc[nt][3] * inv1);
    }
}

// ---------------- launch ----------------
extern "C" void kernel_launch(void* const* d_in, const int* in_sizes, int n_in,
                              void* d_out, int out_size)
{
    (void)in_sizes; (void)n_in; (void)out_size;
    const float* x    = (const float*)d_in[0];
    const float* cosb = (const float*)d_in[1];
    const float* sinb = (const float*)d_in[2];
    const float* wq   = (const float*)d_in[3];
    const float* wk   = (const float*)d_in[4];
    const float* wv   = (const float*)d_in[5];
    const float* wo   = (const float*)d_in[6];
    float* out = (float*)d_out;

    float *qb, *kb, *vb, *ab;
    cudaGetSymbolAddress((void**)&qb, g_q);
    cudaGetSymbolAddress((void**)&kb, g_k);
    cudaGetSymbolAddress((void**)&vb, g_v);
    cudaGetSymbolAddress((void**)&ab, g_att);

    cudaFuncSetAttribute(flash_tc_kernel, cudaFuncAttributeMaxDynamicSharedMemorySize,
                         FLASH_SMEM_BYTES);

    // fused QKV projections (tf32 tensor cores; RoPE fused into q/k epilogues)
    {
        dim3 g((QDIM + 2 * KVDIM) / BN, N_TOK / BM);   // (24, 32)
        qkv_gemm_kernel<<<g, 256>>>(x, wq, wk, wv, qb, kb, vb, cosb, sinb);
    }
    // attention (tensor-core flash)
    {
        dim3 g(S_LEN / 64, NH, 2);
        flash_tc_kernel<<<g, 256, FLASH_SMEM_BYTES>>>(qb, kb, vb, ab);
    }
    // output projection (streaming stores to final output)
    {
        dim3 go(D_MODEL / BN, N_TOK / BM);
        gemm_tf32_kernel<<<go, 256>>>(ab, wo, out, D_MODEL, D_MODEL);
    }
}

// round 17
// speedup vs baseline: 1.0344x; 1.0344x over previous
#include <cuda_runtime.h>
#include <cstdint>

#define S_LEN   2048
#define D_MODEL 2048
#define N_TOK   4096        // B*S
#define NH      16
#define NKV     4
#define HD      128
#define QDIM    (NH*HD)     // 2048
#define KVDIM   (NKV*HD)    // 512

// ---------------- scratch (static device globals; no allocation) ----------------
__device__ float g_q[(size_t)N_TOK * QDIM];
__device__ float g_k[(size_t)N_TOK * KVDIM];
__device__ float g_v[(size_t)N_TOK * KVDIM];
__device__ float g_att[(size_t)N_TOK * QDIM];

// ============================================================================
// shared tf32 helpers
// ============================================================================
__device__ __forceinline__ uint32_t f32_to_tf32(float x) {
    uint32_t r;
    asm("cvt.rna.tf32.f32 %0, %1;" : "=r"(r) : "f"(x));
    return r;
}

__device__ __forceinline__ uint32_t smem_u32(const void* p) {
    return (uint32_t)__cvta_generic_to_shared(p);
}

// ldmatrix.x4 on 32-bit data: each 8x8 b16 matrix == 8x4 tf32 tile.
// Lane i of matrix m receives element [i/4][i%4] — exactly the tf32 mma
// A-fragment layout (a0..a3 = the four 8x4 tiles of a 16x8 A block).
__device__ __forceinline__ void ldmatrix_x4(
    uint32_t& r0, uint32_t& r1, uint32_t& r2, uint32_t& r3, uint32_t addr)
{
    asm volatile("ldmatrix.sync.aligned.m8n8.x4.shared.b16 {%0,%1,%2,%3}, [%4];"
        : "=r"(r0), "=r"(r1), "=r"(r2), "=r"(r3) : "r"(addr));
}

__device__ __forceinline__ void mma_tf32(
    float& c0, float& c1, float& c2, float& c3,
    uint32_t a0, uint32_t a1, uint32_t a2, uint32_t a3,
    uint32_t b0, uint32_t b1)
{
    asm volatile(
        "mma.sync.aligned.m16n8k8.row.col.f32.tf32.tf32.f32 "
        "{%0,%1,%2,%3}, {%4,%5,%6,%7}, {%8,%9}, {%0,%1,%2,%3};\n"
        : "+f"(c0), "+f"(c1), "+f"(c2), "+f"(c3)
        : "r"(a0), "r"(a1), "r"(a2), "r"(a3), "r"(b0), "r"(b1));
}

// ============================================================================
// tf32 tensor-core GEMM body: C[M,N] = A[M,K] @ B[K,N], row-major fp32 in/out.
// 128x128 tile, BK=32, 256 threads (8 warps 2m x 4n), warp tile 64x32.
// Double-buffered smem; A-fragments via ldmatrix.x4 (1 instr per 16x8 block).
// ============================================================================
#define BM 128
#define BN 128
#define BK 32
#define AS_LD 36    // row stride 144B: 16B-aligned, 8 rows cover 32 banks
#define BS_LD 136   // b-frag banks (8*tg+ga) all distinct
#define AS_SZ (BM * AS_LD)
#define BS_SZ (BK * BS_LD)

struct GemmSmem {
    uint32_t As[2][AS_SZ];
    uint32_t Bs[2][BS_SZ];
};

__device__ __forceinline__ void gemm_tf32_body(
    GemmSmem& sm,
    const float* __restrict__ A, const float* __restrict__ B, float* __restrict__ C,
    int N, int K, int m0, int n0,
    const float* __restrict__ ropeCos, const float* __restrict__ ropeSin, int doRope,
    int streamC)
{
    const int tid  = threadIdx.x;
    const int lane = tid & 31;
    const int wid  = tid >> 5;
    const int warp_m = wid >> 2;
    const int warp_n = wid & 3;
    const int ga = lane >> 2;
    const int tg = lane & 3;

    // loader indices (constant across tiles)
    const int arow0 = tid >> 3, ac4 = tid & 7;     // + i*32 rows
    const int brow0 = tid >> 5, bc4 = tid & 31;    // + i*8 rows

    // ldmatrix lane addressing: row = base + (lane&15), col quad = (lane>>4)
    const uint32_t as_u32 = smem_u32(&sm.As[0][0]);
    const uint32_t a_lane_base = as_u32
        + (uint32_t)(warp_m * 64 + (lane & 15)) * (AS_LD * 4)
        + (uint32_t)(lane >> 4) * 16;

    float acc[4][4][4];
    #pragma unroll
    for (int i = 0; i < 4; i++)
        #pragma unroll
        for (int j = 0; j < 4; j++)
            #pragma unroll
            for (int r = 0; r < 4; r++) acc[i][j][r] = 0.f;

    float4 aw[4], bw[4];
    // prologue: LDG tile 0, STS into buf 0
    #pragma unroll
    for (int i = 0; i < 4; i++) {
        aw[i] = *(const float4*)&A[(size_t)(m0 + arow0 + i * 32) * K + ac4 * 4];
        bw[i] = *(const float4*)&B[(size_t)(brow0 + i * 8) * N + n0 + bc4 * 4];
    }
    #pragma unroll
    for (int i = 0; i < 4; i++) {
        uint32_t* ap = &sm.As[0][(arow0 + i * 32) * AS_LD + ac4 * 4];
        ap[0] = f32_to_tf32(aw[i].x); ap[1] = f32_to_tf32(aw[i].y);
        ap[2] = f32_to_tf32(aw[i].z); ap[3] = f32_to_tf32(aw[i].w);
        uint32_t* bp = &sm.Bs[0][(brow0 + i * 8) * BS_LD + bc4 * 4];
        bp[0] = f32_to_tf32(bw[i].x); bp[1] = f32_to_tf32(bw[i].y);
        bp[2] = f32_to_tf32(bw[i].z); bp[3] = f32_to_tf32(bw[i].w);
    }
    __syncthreads();

    for (int k0 = 0; k0 < K; k0 += BK) {
        const int buf = (k0 / BK) & 1;
        const int kn = k0 + BK;
        const bool more = (kn < K);
        const uint32_t a_buf_base = a_lane_base + (uint32_t)buf * (AS_SZ * 4);

        // LDG next tile (latency hides under MMA below)
        if (more) {
            #pragma unroll
            for (int i = 0; i < 4; i++) {
                aw[i] = *(const float4*)&A[(size_t)(m0 + arow0 + i * 32) * K + kn + ac4 * 4];
                bw[i] = *(const float4*)&B[(size_t)(kn + brow0 + i * 8) * N + n0 + bc4 * 4];
            }
        }

        // MMA on current buffer
        #pragma unroll
        for (int ks = 0; ks < BK / 8; ks++) {
            const int kk = ks * 8;
            uint32_t afr[4][4];
            #pragma unroll
            for (int mt = 0; mt < 4; mt++)
                ldmatrix_x4(afr[mt][0], afr[mt][1], afr[mt][2], afr[mt][3],
                            a_buf_base + (uint32_t)(mt * 16 * AS_LD + kk) * 4);
            uint32_t bfr[4][2];
            #pragma unroll
            for (int nt = 0; nt < 4; nt++) {
                const int ncol = warp_n * 32 + nt * 8;
                bfr[nt][0] = sm.Bs[buf][(kk + tg)     * BS_LD + ncol + ga];
                bfr[nt][1] = sm.Bs[buf][(kk + 4 + tg) * BS_LD + ncol + ga];
            }
            #pragma unroll
            for (int mt = 0; mt < 4; mt++)
                #pragma unroll
                for (int nt = 0; nt < 4; nt++)
                    mma_tf32(acc[mt][nt][0], acc[mt][nt][1], acc[mt][nt][2], acc[mt][nt][3],
                             afr[mt][0], afr[mt][1], afr[mt][2], afr[mt][3],
                             bfr[nt][0], bfr[nt][1]);
        }

        // STS next tile into other buffer (overlaps the tail of MMA issue)
        if (more) {
            const int nb = buf ^ 1;
            #pragma unroll
            for (int i = 0; i < 4; i++) {
                uint32_t* ap = &sm.As[nb][(arow0 + i * 32) * AS_LD + ac4 * 4];
                ap[0] = f32_to_tf32(aw[i].x); ap[1] = f32_to_tf32(aw[i].y);
                ap[2] = f32_to_tf32(aw[i].z); ap[3] = f32_to_tf32(aw[i].w);
                uint32_t* bp = &sm.Bs[nb][(brow0 + i * 8) * BS_LD + bc4 * 4];
                bp[0] = f32_to_tf32(bw[i].x); bp[1] = f32_to_tf32(bw[i].y);
                bp[2] = f32_to_tf32(bw[i].z); bp[3] = f32_to_tf32(bw[i].w);
            }
        }
        __syncthreads();
    }

    // ---- epilogue (optional fused RoPE: rotate (c0,c1)/(c2,c3) pairs) ----
    #pragma unroll
    for (int mt = 0; mt < 4; mt++) {
        const int mrow = m0 + warp_m * 64 + mt * 16;
        #pragma unroll
        for (int nt = 0; nt < 4; nt++) {
            const int ncol = n0 + warp_n * 32 + nt * 8;
            float o0 = acc[mt][nt][0], o1 = acc[mt][nt][1];
            float o2 = acc[mt][nt][2], o3 = acc[mt][nt][3];
            if (doRope) {
                // thread's cols are ncol+2*tg, ncol+2*tg+1 -> pair idx ((ncol&127)>>1)+tg
                const int pi = ((ncol & 127) >> 1) + tg;
                const int s0 = (mrow + ga) & (S_LEN - 1);
                const int s1 = (mrow + 8 + ga) & (S_LEN - 1);
                const float c0 = ropeCos[s0 * 64 + pi], sn0 = ropeSin[s0 * 64 + pi];
                const float c1 = ropeCos[s1 * 64 + pi], sn1 = ropeSin[s1 * 64 + pi];
                const float r0 = o0 * c0 - o1 * sn0, i0 = o0 * sn0 + o1 * c0;
                const float r1 = o2 * c1 - o3 * sn1, i1 = o2 * sn1 + o3 * c1;
                o0 = r0; o1 = i0; o2 = r1; o3 = i1;
            }
            float2* p0 = (float2*)&C[(size_t)(mrow + ga) * N + ncol + 2 * tg];
            float2* p1 = (float2*)&C[(size_t)(mrow + 8 + ga) * N + ncol + 2 * tg];
            if (streamC) {   // final output: never re-read -> evict-first
                __stcs(p0, make_float2(o0, o1));
                __stcs(p1, make_float2(o2, o3));
            } else {
                *p0 = make_float2(o0, o1);
                *p1 = make_float2(o2, o3);
            }
        }
    }
}

// fused QKV projection: grid.x = 16 (q) + 4 (k) + 4 (v) = 24 n-blocks
__global__ __launch_bounds__(256, 2) void qkv_gemm_kernel(
    const float* __restrict__ x,
    const float* __restrict__ wq, const float* __restrict__ wk, const float* __restrict__ wv,
    float* __restrict__ qb, float* __restrict__ kb, float* __restrict__ vb,
    const float* __restrict__ ropeCos, const float* __restrict__ ropeSin)
{
    __shared__ GemmSmem sm;
    const int bx = blockIdx.x;
    const float* B; float* C; int N; int doRope; int nblk;
    if (bx < 16)      { B = wq; C = qb; N = QDIM;  doRope = 1; nblk = bx; }
    else if (bx < 20) { B = wk; C = kb; N = KVDIM; doRope = 1; nblk = bx - 16; }
    else              { B = wv; C = vb; N = KVDIM; doRope = 0; nblk = bx - 20; }
    gemm_tf32_body(sm, x, B, C, N, D_MODEL, blockIdx.y * BM, nblk * BN,
                   ropeCos, ropeSin, doRope, 0);
}

// plain GEMM (wo projection; streaming C stores)
__global__ __launch_bounds__(256, 2) void gemm_tf32_kernel(
    const float* __restrict__ A, const float* __restrict__ B, float* __restrict__ C,
    int N, int K)
{
    __shared__ GemmSmem sm;
    gemm_tf32_body(sm, A, B, C, N, K, blockIdx.y * BM, blockIdx.x * BN,
                   nullptr, nullptr, 0, 1);
}

// ============================================================================
// tensor-core flash attention (causal, GQA), tf32 mma, fp32 online softmax
// in base-2 domain. BM=BN=64, HD=128, 256 threads = 8 warps.
// Q/P a-fragments via ldmatrix.x4; pipelined K/V register buffer tbuf[8].
// ============================================================================
#define FQ_LD 132
#define FK_LD 72
#define FV_LD 136
#define FP_LD 68
#define OFF_Q  0
#define OFF_KV (64 * FQ_LD)                 // 8448
#define OFF_P  (OFF_KV + 128 * FK_LD)       // 17664
#define OFF_RM (OFF_P + 64 * FP_LD)         // 22016  red_max[2][64]
#define OFF_RS (OFF_RM + 128)               // 22144  red_sum[2][64]
#define FLASH_SMEM_BYTES ((OFF_RS + 128) * 4)   // 89088

__global__ __launch_bounds__(256, 2) void flash_tc_kernel(
    const float* __restrict__ Q, const float* __restrict__ K,
    const float* __restrict__ V, float* __restrict__ O)
{
    extern __shared__ uint32_t smw[];
    uint32_t* Qs  = smw + OFF_Q;    // [64][132] tf32, row-major [tok][dim]
    uint32_t* KVs = smw + OFF_KV;   // K: [dim][tok^swz] LD 72; V: [tok][dim] LD 136
    uint32_t* Ps  = smw + OFF_P;    // [64][68] tf32
    float* red_m = (float*)(smw + OFF_RM);
    float* red_s = (float*)(smw + OFF_RS);

    const int tid  = threadIdx.x;
    const int lane = tid & 31;
    const int wid  = tid >> 5;
    const int warp_m = wid & 3;
    const int warp_n = wid >> 2;          // 0..1
    const int ga = lane >> 2, tg = lane & 3;
    const int slab = warp_m * 16;

    const int mb = gridDim.x - 1 - blockIdx.x;   // longest CTAs first
    const int h  = blockIdx.y, b = blockIdx.z;
    const int kvh = h >> 2;
    // 1/sqrt(128) * log2(e): scores land directly in base-2 log domain
    const float scale2 = 0.08838834764831845f * 1.4426950408889634f;

    // loader indices (constant across tiles): row lr, dim-quad ld4
    const int lr0 = tid >> 5, ld4 = tid & 31;    // + p*8 rows
    const size_t kvcol = (size_t)kvh * HD + ld4 * 4;

    // ldmatrix lane addressing for Q/P fragments
    const uint32_t q_lane_base = smem_u32(Qs)
        + (uint32_t)(slab + (lane & 15)) * (FQ_LD * 4) + (uint32_t)(lane >> 4) * 16;
    const uint32_t p_lane_base = smem_u32(Ps)
        + (uint32_t)(slab + (lane & 15)) * (FP_LD * 4) + (uint32_t)(lane >> 4) * 16;

    // ---- load Q tile [64][128] -> Qs (tf32); read-once -> streaming loads ----
    const int qrow0 = b * S_LEN + mb * 64;
    #pragma unroll
    for (int p = 0; p < 8; p++) {
        const int r = lr0 + p * 8;
        const float4 q = __ldcs((const float4*)&Q[(size_t)(qrow0 + r) * QDIM + h * HD + ld4 * 4]);
        uint32_t* qp = &Qs[r * FQ_LD + ld4 * 4];
        qp[0] = f32_to_tf32(q.x); qp[1] = f32_to_tf32(q.y);
        qp[2] = f32_to_tf32(q.z); qp[3] = f32_to_tf32(q.w);
    }

    float m_i[2] = {-1e30f, -1e30f}, l_i[2] = {0.f, 0.f};
    float oacc[8][4];
    #pragma unroll
    for (int t = 0; t < 8; t++)
        #pragma unroll
        for (int r = 0; r < 4; r++) oacc[t][r] = 0.f;

    const int grow0 = mb * 64 + slab + ga;      // global q row (within seq)
    const int grow1 = grow0 + 8;

    // ---- pipeline prologue: prefetch K tile 0 into tbuf ----
    float4 tbuf[8];
    #pragma unroll
    for (int p = 0; p < 8; p++)
        tbuf[p] = *(const float4*)&K[(size_t)(b * S_LEN + lr0 + p * 8) * KVDIM + kvcol];

    for (int kb = 0; kb <= mb; kb++) {
        const int t0 = kb * 64;
        __syncthreads();   // prev PV mma done with KVs/Ps

        // ---- K tile (prefetched in tbuf) -> KVs, d-major with XOR swizzle ----
        #pragma unroll
        for (int p = 0; p < 8; p++) {
            const int r = lr0 + p * 8;
            const int rx = r ^ ld4;             // swizzle: s(d) = (d>>2)&31
            KVs[(ld4 * 4 + 0) * FK_LD + rx] = f32_to_tf32(tbuf[p].x);
            KVs[(ld4 * 4 + 1) * FK_LD + rx] = f32_to_tf32(tbuf[p].y);
            KVs[(ld4 * 4 + 2) * FK_LD + rx] = f32_to_tf32(tbuf[p].z);
            KVs[(ld4 * 4 + 3) * FK_LD + rx] = f32_to_tf32(tbuf[p].w);
        }
        __syncthreads();

        // ---- S = Q @ K^T (64x64), warp tile 16x32 ----
        float sc[4][4];
        #pragma unroll
        for (int nt = 0; nt < 4; nt++)
            #pragma unroll
            for (int j = 0; j < 4; j++) sc[nt][j] = 0.f;

        #pragma unroll
        for (int ks = 0; ks < 16; ks++) {
            const int kk = ks * 8;
            uint32_t a0, a1, a2, a3;
            ldmatrix_x4(a0, a1, a2, a3, q_lane_base + (uint32_t)kk * 4);
            const int s0 = (2 * ks) & 31, s1 = (2 * ks + 1) & 31;
            #pragma unroll
            for (int nt = 0; nt < 4; nt++) {
                const int ncol = warp_n * 32 + nt * 8;
                const uint32_t b0 = KVs[(kk + tg)     * FK_LD + ((ncol + ga) ^ s0)];
                const uint32_t b1 = KVs[(kk + 4 + tg) * FK_LD + ((ncol + ga) ^ s1)];
                mma_tf32(sc[nt][0], sc[nt][1], sc[nt][2], sc[nt][3],
                         a0, a1, a2, a3, b0, b1);
            }
        }

        // ---- prefetch V tile into tbuf (latency hides under softmax) ----
        #pragma unroll
        for (int p = 0; p < 8; p++)
            tbuf[p] = *(const float4*)&V[(size_t)(b * S_LEN + t0 + lr0 + p * 8) * KVDIM + kvcol];

        // ---- scale into base-2 domain + causal mask (global col > row) ----
        #pragma unroll
        for (int nt = 0; nt < 4; nt++) {
            const int c0 = t0 + warp_n * 32 + nt * 8 + 2 * tg;
            sc[nt][0] = (c0     > grow0) ? -1e30f : sc[nt][0] * scale2;
            sc[nt][1] = (c0 + 1 > grow0) ? -1e30f : sc[nt][1] * scale2;
            sc[nt][2] = (c0     > grow1) ? -1e30f : sc[nt][2] * scale2;
            sc[nt][3] = (c0 + 1 > grow1) ? -1e30f : sc[nt][3] * scale2;
        }

        // ---- row max: 4-lane shuffle + cross-warp smem exchange ----
        float pm0 = -1e30f, pm1 = -1e30f;
        #pragma unroll
        for (int nt = 0; nt < 4; nt++) {
            pm0 = fmaxf(pm0, fmaxf(sc[nt][0], sc[nt][1]));
            pm1 = fmaxf(pm1, fmaxf(sc[nt][2], sc[nt][3]));
        }
        pm0 = fmaxf(pm0, __shfl_xor_sync(0xffffffffu, pm0, 1));
        pm0 = fmaxf(pm0, __shfl_xor_sync(0xffffffffu, pm0, 2));
        pm1 = fmaxf(pm1, __shfl_xor_sync(0xffffffffu, pm1, 1));
        pm1 = fmaxf(pm1, __shfl_xor_sync(0xffffffffu, pm1, 2));
        if (tg == 0) {
            red_m[warp_n * 64 + slab + ga]     = pm0;
            red_m[warp_n * 64 + slab + 8 + ga] = pm1;
        }
        __syncthreads();   // also: all S-mma reads of K complete -> KVs free

        const float mnew0 = fmaxf(m_i[0], fmaxf(red_m[slab + ga],     red_m[64 + slab + ga]));
        const float mnew1 = fmaxf(m_i[1], fmaxf(red_m[slab + 8 + ga], red_m[64 + slab + 8 + ga]));
        const float alpha0 = exp2f(m_i[0] - mnew0);
        const float alpha1 = exp2f(m_i[1] - mnew1);

        // ---- exp2, write P (tf32), partial sums ----
        float ps0 = 0.f, ps1 = 0.f;
        #pragma unroll
        for (int nt = 0; nt < 4; nt++) {
            sc[nt][0] = exp2f(sc[nt][0] - mnew0);
            sc[nt][1] = exp2f(sc[nt][1] - mnew0);
            sc[nt][2] = exp2f(sc[nt][2] - mnew1);
            sc[nt][3] = exp2f(sc[nt][3] - mnew1);
            ps0 += sc[nt][0] + sc[nt][1];
            ps1 += sc[nt][2] + sc[nt][3];
            const int pc = warp_n * 32 + nt * 8 + 2 * tg;
            uint2 u0 = make_uint2(f32_to_tf32(sc[nt][0]), f32_to_tf32(sc[nt][1]));
            uint2 u1 = make_uint2(f32_to_tf32(sc[nt][2]), f32_to_tf32(sc[nt][3]));
            *(uint2*)&Ps[(slab + ga)     * FP_LD + pc] = u0;
            *(uint2*)&Ps[(slab + 8 + ga) * FP_LD + pc] = u1;
        }
        ps0 += __shfl_xor_sync(0xffffffffu, ps0, 1);
        ps0 += __shfl_xor_sync(0xffffffffu, ps0, 2);
        ps1 += __shfl_xor_sync(0xffffffffu, ps1, 1);
        ps1 += __shfl_xor_sync(0xffffffffu, ps1, 2);
        if (tg == 0) {
            red_s[warp_n * 64 + slab + ga]     = ps0;
            red_s[warp_n * 64 + slab + 8 + ga] = ps1;
        }

        // ---- V tile (tbuf) -> KVs (natural [tok][dim], LD 136) ----
        #pragma unroll
        for (int p = 0; p < 8; p++) {
            const int r = lr0 + p * 8;
            uint4 u = make_uint4(f32_to_tf32(tbuf[p].x), f32_to_tf32(tbuf[p].y),
                                 f32_to_tf32(tbuf[p].z), f32_to_tf32(tbuf[p].w));
            *(uint4*)&KVs[r * FV_LD + ld4 * 4] = u;
        }

        // ---- prefetch NEXT K tile into tbuf (hides under PV MMA) ----
        if (kb < mb) {
            #pragma unroll
            for (int p = 0; p < 8; p++)
                tbuf[p] = *(const float4*)&K[(size_t)(b * S_LEN + t0 + 64 + lr0 + p * 8) * KVDIM + kvcol];
        }
        __syncthreads();   // Ps + red_s + V ready

        const float rs0 = red_s[slab + ga]     + red_s[64 + slab + ga];
        const float rs1 = red_s[slab + 8 + ga] + red_s[64 + slab + 8 + ga];
        l_i[0] = l_i[0] * alpha0 + rs0;  m_i[0] = mnew0;
        l_i[1] = l_i[1] * alpha1 + rs1;  m_i[1] = mnew1;
        #pragma unroll
        for (int t = 0; t < 8; t++) {
            oacc[t][0] *= alpha0; oacc[t][1] *= alpha0;
            oacc[t][2] *= alpha1; oacc[t][3] *= alpha1;
        }

        // ---- O += P @ V (64x128, k=64), warp tile 16x64 ----
        #pragma unroll
        for (int ks = 0; ks < 8; ks++) {
            const int kk = ks * 8;
            uint32_t a0, a1, a2, a3;
            ldmatrix_x4(a0, a1, a2, a3, p_lane_base + (uint32_t)kk * 4);
            #pragma unroll
            for (int nt = 0; nt < 8; nt++) {
                const int ncol = warp_n * 64 + nt * 8;
                const uint32_t b0 = KVs[(kk + tg)     * FV_LD + ncol + ga];
                const uint32_t b1 = KVs[(kk + 4 + tg) * FV_LD + ncol + ga];
                mma_tf32(oacc[nt][0], oacc[nt][1], oacc[nt][2], oacc[nt][3],
                         a0, a1, a2, a3, b0, b1);
            }
        }
    }

    // ---- normalize + write ----
    const float inv0 = 1.f / l_i[0], inv1 = 1.f / l_i[1];
    const size_t orow0 = (size_t)(b * S_LEN + grow0) * QDIM + h * HD;
    const size_t orow1 = (size_t)(b * S_LEN + grow1) * QDIM + h * HD;
    #pragma unroll
    for (int nt = 0; nt < 8; nt++) {
        const int col = warp_n * 64 + nt * 8 + 2 * tg;
        *(float2*)&O[orow0 + col] = make_float2(oacc[nt][0] * inv0, oacc[nt][1] * inv0);
        *(float2*)&O[orow1 + col] = make_float2(oacc[nt][2] * inv1, oacc[nt][3] * inv1);
    }
}

// ---------------- launch ----------------
extern "C" void kernel_launch(void* const* d_in, const int* in_sizes, int n_in,
                              void* d_out, int out_size)
{
    (void)in_sizes; (void)n_in; (void)out_size;
    const float* x    = (const float*)d_in[0];
    const float* cosb = (const float*)d_in[1];
    const float* sinb = (const float*)d_in[2];
    const float* wq   = (const float*)d_in[3];
    const float* wk   = (const float*)d_in[4];
    const float* wv   = (const float*)d_in[5];
    const float* wo   = (const float*)d_in[6];
    float* out = (float*)d_out;

    float *qb, *kb, *vb, *ab;
    cudaGetSymbolAddress((void**)&qb, g_q);
    cudaGetSymbolAddress((void**)&kb, g_k);
    cudaGetSymbolAddress((void**)&vb, g_v);
    cudaGetSymbolAddress((void**)&ab, g_att);

    cudaFuncSetAttribute(flash_tc_kernel, cudaFuncAttributeMaxDynamicSharedMemorySize,
                         FLASH_SMEM_BYTES);

    // fused QKV projections (tf32 tensor cores; RoPE fused into q/k epilogues)
    {
        dim3 g((QDIM + 2 * KVDIM) / BN, N_TOK / BM);   // (24, 32)
        qkv_gemm_kernel<<<g, 256>>>(x, wq, wk, wv, qb, kb, vb, cosb, sinb);
    }
    // attention (tensor-core flash)
    {
        dim3 g(S_LEN / 64, NH, 2);
        flash_tc_kernel<<<g, 256, FLASH_SMEM_BYTES>>>(qb, kb, vb, ab);
    }
    // output projection (streaming stores to final output)
    {
        dim3 go(D_MODEL / BN, N_TOK / BM);
        gemm_tf32_kernel<<<go, 256>>>(ab, wo, out, D_MODEL, D_MODEL);
    }
}